// round 2
// baseline (speedup 1.0000x reference)
#include <cuda_runtime.h>
#include <cuda_bf16.h>
#include <math.h>

#define B_  32
#define T_  512
#define D_  1024
#define UN_ 1024
#define NG_ 3072
#define M_  (B_*T_)
#define NBLK 128

// ---------------- device scratch ----------------
__device__ __align__(16) float g_xp[(size_t)M_ * NG_];        // 192 MB
__device__ __align__(16) float g_bsum[NG_];
__device__ __align__(16) float g_h[B_ * UN_];
__device__ __align__(16) float g_z[B_ * UN_];
__device__ __align__(16) float g_rh[B_ * UN_];
__device__ __align__(16) float g_p1[4 * B_ * UN_];            // [g*2+ks][b][u]
__device__ __align__(16) float g_p2[4 * B_ * UN_];            // [ks2][b][u]
__device__ unsigned long long g_c1[64];
__device__ unsigned long long g_c2[32];
__device__ unsigned long long g_barcnt;

// ---------------- bias column sums ----------------
__global__ void k_bsum(const float* __restrict__ b) {
    int c = blockIdx.x * 256 + threadIdx.x;
    float acc = 0.f;
    for (int k = 0; k < D_; k++) acc += b[(size_t)k * NG_ + c];
    g_bsum[c] = acc;
}

// ---------------- init: h0 -> g_h, reset counters ----------------
__global__ void k_init(const float* __restrict__ h0) {
    int i = blockIdx.x * 256 + threadIdx.x;
    if (i < B_ * UN_) g_h[i] = h0[i];
    if (blockIdx.x == 0) {
        if (threadIdx.x < 64) g_c1[threadIdx.x] = 0ULL;
        if (threadIdx.x < 32) g_c2[threadIdx.x] = 0ULL;
        if (threadIdx.x == 0) g_barcnt = 0ULL;
    }
}

// ---------------- SGEMM: xp = x @ W  (128x128 tile, 8x8/thread) ----------------
__global__ void __launch_bounds__(256) k_gemm(const float* __restrict__ A,
                                              const float* __restrict__ Bm) {
    __shared__ float As[8][128];
    __shared__ float Bs[8][128];
    const int m0 = blockIdx.y * 128;
    const int n0 = blockIdx.x * 128;
    const int tx = threadIdx.x & 15;
    const int ty = threadIdx.x >> 4;
    const int aRow = threadIdx.x >> 1;
    const int aCol = (threadIdx.x & 1) * 4;
    const int bRow = threadIdx.x >> 5;
    const int bCol = (threadIdx.x & 31) * 4;

    float acc[8][8];
#pragma unroll
    for (int i = 0; i < 8; i++)
#pragma unroll
        for (int j = 0; j < 8; j++) acc[i][j] = 0.f;

    for (int k0 = 0; k0 < D_; k0 += 8) {
        float4 av = *(const float4*)(A + (size_t)(m0 + aRow) * D_ + k0 + aCol);
        As[aCol + 0][aRow] = av.x;
        As[aCol + 1][aRow] = av.y;
        As[aCol + 2][aRow] = av.z;
        As[aCol + 3][aRow] = av.w;
        *(float4*)&Bs[bRow][bCol] =
            *(const float4*)(Bm + (size_t)(k0 + bRow) * NG_ + n0 + bCol);
        __syncthreads();
#pragma unroll
        for (int kk = 0; kk < 8; kk++) {
            float ar[8], br[8];
            *(float4*)(ar)     = *(float4*)&As[kk][ty * 8];
            *(float4*)(ar + 4) = *(float4*)&As[kk][ty * 8 + 4];
            *(float4*)(br)     = *(float4*)&Bs[kk][tx * 8];
            *(float4*)(br + 4) = *(float4*)&Bs[kk][tx * 8 + 4];
#pragma unroll
            for (int i = 0; i < 8; i++)
#pragma unroll
                for (int j = 0; j < 8; j++) acc[i][j] += ar[i] * br[j];
        }
        __syncthreads();
    }
#pragma unroll
    for (int i = 0; i < 8; i++) {
        size_t row = (size_t)(m0 + ty * 8 + i);
        float4 v0 = {acc[i][0], acc[i][1], acc[i][2], acc[i][3]};
        float4 v1 = {acc[i][4], acc[i][5], acc[i][6], acc[i][7]};
        *(float4*)&g_xp[row * NG_ + n0 + tx * 8]     = v0;
        *(float4*)&g_xp[row * NG_ + n0 + tx * 8 + 4] = v1;
    }
}

// ---------------- grid barrier ----------------
__device__ __forceinline__ void gridbar(unsigned long long target) {
    __syncthreads();
    if (threadIdx.x == 0) {
        __threadfence();
        atomicAdd(&g_barcnt, 1ULL);
        while (*((volatile unsigned long long*)&g_barcnt) < target) __nanosleep(64);
    }
    __syncthreads();
}

// ---------------- persistent GRU recurrence ----------------
// smem layout (floats): Ug[512*32] | Uh2[256*32] | hsT[128*32] | red[3*64*16]
#define SM_UG   0
#define SM_UH2  16384
#define SM_HST  24576
#define SM_RED  28672
#define SM_FLOATS 31744

__global__ void __launch_bounds__(256, 1) k_gru(const float* __restrict__ U,
                                                float* __restrict__ out) {
    extern __shared__ float sm[];
    float* Ug  = sm + SM_UG;
    float* Uh2 = sm + SM_UH2;
    float* hsT = sm + SM_HST;
    float* red = sm + SM_RED;
    __shared__ int sflag;

    const int bid = blockIdx.x, tid = threadIdx.x;
    // P1 role: gate g, u-tile (32 wide), k half (512)
    const int g    = bid >> 6;
    const int ut   = (bid >> 1) & 31;
    const int ks   = bid & 1;
    const int u0p1 = ut * 32;
    const int k0p1 = ks * 512;
    // P2 role: u-tile (32 wide), k quarter (256)
    const int ut2  = bid >> 2;
    const int ks2  = bid & 3;
    const int u0p2 = ut2 * 32;
    const int k0p2 = ks2 * 256;

    // preload U slices into smem (held for all 512 steps)
    for (int i = tid; i < 512 * 8; i += 256) {
        int kk = i >> 3, uu4 = (i & 7) * 4;
        *(float4*)&Ug[kk * 32 + uu4] =
            *(const float4*)&U[(size_t)(k0p1 + kk) * NG_ + g * UN_ + u0p1 + uu4];
    }
    for (int i = tid; i < 256 * 8; i += 256) {
        int kk = i >> 3, uu4 = (i & 7) * 4;
        *(float4*)&Uh2[kk * 32 + uu4] =
            *(const float4*)&U[(size_t)(k0p2 + kk) * NG_ + 2 * UN_ + u0p2 + uu4];
    }
    __syncthreads();

    const int uq = tid & 7;          // 8 u-groups of 4
    const int bq = (tid >> 3) & 7;   // 8 b-groups of 4
    const int kx = tid >> 6;         // 4-way in-block k split
    const int r64 = tid & 63;

    unsigned long long epoch = 0;

    for (int t = 0; t < T_; t++) {
        // ================= P1: z,r partials =================
        float acc[4][4];
#pragma unroll
        for (int i = 0; i < 4; i++)
#pragma unroll
            for (int j = 0; j < 4; j++) acc[i][j] = 0.f;

        for (int kc = 0; kc < 4; kc++) {
            const int kbase = k0p1 + kc * 128;
            __syncthreads();
            for (int i = tid; i < 1024; i += 256) {
                int b = i & 31, k4 = i >> 5;
                float4 hv = __ldcg((const float4*)&g_h[b * UN_ + kbase + k4 * 4]);
                hsT[(k4 * 4 + 0) * 32 + b] = hv.x;
                hsT[(k4 * 4 + 1) * 32 + b] = hv.y;
                hsT[(k4 * 4 + 2) * 32 + b] = hv.z;
                hsT[(k4 * 4 + 3) * 32 + b] = hv.w;
            }
            __syncthreads();
#pragma unroll 8
            for (int kk = kx; kk < 128; kk += 4) {
                float uv[4], hv[4];
                *(float4*)uv = *(float4*)&Ug[(kc * 128 + kk) * 32 + uq * 4];
                *(float4*)hv = *(float4*)&hsT[kk * 32 + bq * 4];
#pragma unroll
                for (int i = 0; i < 4; i++)
#pragma unroll
                    for (int j = 0; j < 4; j++) acc[i][j] += hv[i] * uv[j];
            }
        }
        __syncthreads();
        if (kx > 0) {
            float* d = &red[((kx - 1) * 64 + r64) * 16];
#pragma unroll
            for (int i = 0; i < 4; i++)
                *(float4*)&d[i * 4] = *(float4*)&acc[i][0];
        }
        __syncthreads();
        if (kx == 0) {
#pragma unroll
            for (int r = 0; r < 3; r++) {
                float* d = &red[(r * 64 + r64) * 16];
#pragma unroll
                for (int i = 0; i < 4; i++)
#pragma unroll
                    for (int j = 0; j < 4; j++) acc[i][j] += d[i * 4 + j];
            }
#pragma unroll
            for (int i = 0; i < 4; i++) {
                float4 v = {acc[i][0], acc[i][1], acc[i][2], acc[i][3]};
                __stcg((float4*)&g_p1[((g * 2 + ks) * B_ + bq * 4 + i) * UN_ + u0p1 + uq * 4], v);
            }
        }
        __syncthreads();
        if (tid == 0) {
            __threadfence();
            unsigned long long old = atomicAdd(&g_c1[g * 32 + ut], 1ULL);
            sflag = (int)(old & 1ULL);
        }
        __syncthreads();
        if (sflag) {
            __threadfence();
            for (int i = tid; i < 1024; i += 256) {
                int b = i >> 5, u = u0p1 + (i & 31);
                float s = __ldcg(&g_p1[((g * 2 + 0) * B_ + b) * UN_ + u]) +
                          __ldcg(&g_p1[((g * 2 + 1) * B_ + b) * UN_ + u]);
                int col = g * UN_ + u;
                s += __ldcg(&g_xp[((size_t)b * T_ + t) * NG_ + col]) + g_bsum[col];
                float sig = 1.f / (1.f + __expf(-s));
                if (g == 0) __stcg(&g_z[b * UN_ + u], sig);
                else        __stcg(&g_rh[b * UN_ + u], sig * __ldcg(&g_h[b * UN_ + u]));
            }
        }
        epoch++; gridbar(epoch * NBLK);

        // ================= P2: hcand partials =================
        float a2[4][4];
#pragma unroll
        for (int i = 0; i < 4; i++)
#pragma unroll
            for (int j = 0; j < 4; j++) a2[i][j] = 0.f;

        for (int kc = 0; kc < 2; kc++) {
            const int kbase = k0p2 + kc * 128;
            __syncthreads();
            for (int i = tid; i < 1024; i += 256) {
                int b = i & 31, k4 = i >> 5;
                float4 hv = __ldcg((const float4*)&g_rh[b * UN_ + kbase + k4 * 4]);
                hsT[(k4 * 4 + 0) * 32 + b] = hv.x;
                hsT[(k4 * 4 + 1) * 32 + b] = hv.y;
                hsT[(k4 * 4 + 2) * 32 + b] = hv.z;
                hsT[(k4 * 4 + 3) * 32 + b] = hv.w;
            }
            __syncthreads();
#pragma unroll 8
            for (int kk = kx; kk < 128; kk += 4) {
                float uv[4], hv[4];
                *(float4*)uv = *(float4*)&Uh2[(kc * 128 + kk) * 32 + uq * 4];
                *(float4*)hv = *(float4*)&hsT[kk * 32 + bq * 4];
#pragma unroll
                for (int i = 0; i < 4; i++)
#pragma unroll
                    for (int j = 0; j < 4; j++) a2[i][j] += hv[i] * uv[j];
            }
        }
        __syncthreads();
        if (kx > 0) {
            float* d = &red[((kx - 1) * 64 + r64) * 16];
#pragma unroll
            for (int i = 0; i < 4; i++)
                *(float4*)&d[i * 4] = *(float4*)&a2[i][0];
        }
        __syncthreads();
        if (kx == 0) {
#pragma unroll
            for (int r = 0; r < 3; r++) {
                float* d = &red[(r * 64 + r64) * 16];
#pragma unroll
                for (int i = 0; i < 4; i++)
#pragma unroll
                    for (int j = 0; j < 4; j++) a2[i][j] += d[i * 4 + j];
            }
#pragma unroll
            for (int i = 0; i < 4; i++) {
                float4 v = {a2[i][0], a2[i][1], a2[i][2], a2[i][3]};
                __stcg((float4*)&g_p2[(ks2 * B_ + bq * 4 + i) * UN_ + u0p2 + uq * 4], v);
            }
        }
        __syncthreads();
        if (tid == 0) {
            __threadfence();
            unsigned long long old = atomicAdd(&g_c2[ut2], 1ULL);
            sflag = ((old & 3ULL) == 3ULL) ? 1 : 0;
        }
        __syncthreads();
        if (sflag) {
            __threadfence();
            for (int i = tid; i < 1024; i += 256) {
                int b = i >> 5, u = u0p2 + (i & 31);
                float s = __ldcg(&g_p2[(0 * B_ + b) * UN_ + u]) +
                          __ldcg(&g_p2[(1 * B_ + b) * UN_ + u]) +
                          __ldcg(&g_p2[(2 * B_ + b) * UN_ + u]) +
                          __ldcg(&g_p2[(3 * B_ + b) * UN_ + u]);
                int col = 2 * UN_ + u;
                s += __ldcg(&g_xp[((size_t)b * T_ + t) * NG_ + col]) + g_bsum[col];
                float hc = tanhf(s);
                float z  = __ldcg(&g_z[b * UN_ + u]);
                float ho = __ldcg(&g_h[b * UN_ + u]);
                float hn = z * ho + (1.f - z) * hc;
                __stcg(&g_h[b * UN_ + u], hn);
                out[((size_t)b * T_ + t) * UN_ + u] = hn;
            }
        }
        epoch++; gridbar(epoch * NBLK);
    }

    // final hidden state hT after outputs
    for (int i = bid * 256 + tid; i < B_ * UN_; i += NBLK * 256)
        out[(size_t)B_ * T_ * UN_ + i] = __ldcg(&g_h[i]);
}

// ---------------- launcher ----------------
extern "C" void kernel_launch(void* const* d_in, const int* in_sizes, int n_in,
                              void* d_out, int out_size) {
    const float* x  = (const float*)d_in[0];
    const float* W  = (const float*)d_in[1];
    const float* U  = (const float*)d_in[2];
    const float* b  = (const float*)d_in[3];
    const float* h0 = (const float*)d_in[4];
    float* out = (float*)d_out;

    static bool attr_done = false;
    if (!attr_done) {
        cudaFuncSetAttribute(k_gru, cudaFuncAttributeMaxDynamicSharedMemorySize,
                             SM_FLOATS * sizeof(float));
        attr_done = true;
    }

    k_bsum<<<NG_ / 256, 256>>>(b);
    k_init<<<NBLK, 256>>>(h0);
    {
        dim3 grid(NG_ / 128, M_ / 128);
        k_gemm<<<grid, 256>>>(x, W);
    }
    k_gru<<<NBLK, 256, SM_FLOATS * sizeof(float)>>>(U, out);
}

// round 3
// speedup vs baseline: 1.2332x; 1.2332x over previous
#include <cuda_runtime.h>
#include <cuda_bf16.h>
#include <math.h>

#define B_  32
#define T_  512
#define D_  1024
#define UN_ 1024
#define NG_ 3072
#define M_  (B_*T_)
#define NBLK 128

typedef unsigned long long ull;

// ---------------- packed f32x2 helpers ----------------
#define FMA2(d, a, b) asm("fma.rn.f32x2 %0, %1, %2, %0;" : "+l"(d) : "l"(a), "l"(b))
#define ADD2(d, v)    asm("add.rn.f32x2 %0, %0, %1;"     : "+l"(d) : "l"(v))
#define DUP2(d, s)    asm("mov.b64 %0, {%1, %1};"        : "=l"(d) : "r"(s))

union F2U { ull u; float f[2]; };

// ---------------- device scratch ----------------
__device__ __align__(16) float g_xp[(size_t)M_ * NG_];        // 192 MB
__device__ __align__(16) float g_bsum[NG_];
__device__ __align__(16) float g_h[B_ * UN_];
__device__ __align__(16) float g_z[B_ * UN_];
__device__ __align__(16) float g_rh[B_ * UN_];
__device__ __align__(16) float g_p1[4 * B_ * UN_];            // [g*2+ks][b][u]
__device__ __align__(16) float g_p2[4 * B_ * UN_];            // [ks2][b][u]
__device__ unsigned long long g_c1[64];
__device__ unsigned long long g_c2[32];
__device__ unsigned long long g_barcnt;

// ---------------- bias column sums ----------------
__global__ void k_bsum(const float* __restrict__ b) {
    int c = blockIdx.x * 256 + threadIdx.x;
    float acc = 0.f;
    for (int k = 0; k < D_; k++) acc += b[(size_t)k * NG_ + c];
    g_bsum[c] = acc;
}

// ---------------- init: h0 -> g_h, reset counters ----------------
__global__ void k_init(const float* __restrict__ h0) {
    int i = blockIdx.x * 256 + threadIdx.x;
    if (i < B_ * UN_) g_h[i] = h0[i];
    if (blockIdx.x == 0) {
        if (threadIdx.x < 64) g_c1[threadIdx.x] = 0ULL;
        if (threadIdx.x < 32) g_c2[threadIdx.x] = 0ULL;
        if (threadIdx.x == 0) g_barcnt = 0ULL;
    }
}

// ---------------- SGEMM: xp = x @ W  (128x128 tile, 8x8/thread, f32x2) ----------------
__global__ void __launch_bounds__(256) k_gemm(const float* __restrict__ A,
                                              const float* __restrict__ Bm) {
    __shared__ float As[8][128];
    __shared__ float Bs[8][128];
    const int m0 = blockIdx.y * 128;
    const int n0 = blockIdx.x * 128;
    const int tx = threadIdx.x & 15;
    const int ty = threadIdx.x >> 4;
    const int aRow = threadIdx.x >> 1;
    const int aCol = (threadIdx.x & 1) * 4;
    const int bRow = threadIdx.x >> 5;
    const int bCol = (threadIdx.x & 31) * 4;

    ull acc2[8][4];
#pragma unroll
    for (int i = 0; i < 8; i++)
#pragma unroll
        for (int j = 0; j < 4; j++) acc2[i][j] = 0ULL;

    for (int k0 = 0; k0 < D_; k0 += 8) {
        float4 av = *(const float4*)(A + (size_t)(m0 + aRow) * D_ + k0 + aCol);
        As[aCol + 0][aRow] = av.x;
        As[aCol + 1][aRow] = av.y;
        As[aCol + 2][aRow] = av.z;
        As[aCol + 3][aRow] = av.w;
        *(float4*)&Bs[bRow][bCol] =
            *(const float4*)(Bm + (size_t)(k0 + bRow) * NG_ + n0 + bCol);
        __syncthreads();
#pragma unroll
        for (int kk = 0; kk < 8; kk++) {
            float a0[8];
            *(float4*)(a0)     = *(float4*)&As[kk][ty * 8];
            *(float4*)(a0 + 4) = *(float4*)&As[kk][ty * 8 + 4];
            ulonglong2 b01 = *(ulonglong2*)&Bs[kk][tx * 8];
            ulonglong2 b23 = *(ulonglong2*)&Bs[kk][tx * 8 + 4];
            ull bp[4] = {b01.x, b01.y, b23.x, b23.y};
#pragma unroll
            for (int i = 0; i < 8; i++) {
                ull ad; DUP2(ad, __float_as_uint(a0[i]));
#pragma unroll
                for (int j = 0; j < 4; j++) FMA2(acc2[i][j], ad, bp[j]);
            }
        }
        __syncthreads();
    }
#pragma unroll
    for (int i = 0; i < 8; i++) {
        size_t row = (size_t)(m0 + ty * 8 + i);
        ulonglong2 v0 = {acc2[i][0], acc2[i][1]};
        ulonglong2 v1 = {acc2[i][2], acc2[i][3]};
        *(ulonglong2*)&g_xp[row * NG_ + n0 + tx * 8]     = v0;
        *(ulonglong2*)&g_xp[row * NG_ + n0 + tx * 8 + 4] = v1;
    }
}

// ---------------- grid barrier ----------------
__device__ __forceinline__ void gridbar(unsigned long long target) {
    __syncthreads();
    if (threadIdx.x == 0) {
        __threadfence();
        atomicAdd(&g_barcnt, 1ULL);
        while (*((volatile unsigned long long*)&g_barcnt) < target) __nanosleep(64);
    }
    __syncthreads();
}

// ---------------- persistent GRU recurrence (512 threads) ----------------
// smem floats: Ug[512*32]=16384 | Uh2[256*32]=8192 | hsT[128*32]=4096 | red 7168
#define SM_UG   0
#define SM_UH2  16384
#define SM_HST  24576
#define SM_RED  28672
#define SM_FLOATS 35840

__global__ void __launch_bounds__(512, 1) k_gru(const float* __restrict__ U,
                                                float* __restrict__ out) {
    extern __shared__ float sm[];
    float* Ug  = sm + SM_UG;
    float* Uh2 = sm + SM_UH2;
    float* hsT = sm + SM_HST;
    ull*   redu = (ull*)(sm + SM_RED);           // [7 slots][8 q][64 lanes]
    __shared__ int sflag;

    const int bid = blockIdx.x, tid = threadIdx.x;
    // P1 role: gate g (z/r), u-tile 32, k half 512
    const int g    = bid >> 6;
    const int ut   = (bid >> 1) & 31;
    const int ks   = bid & 1;
    const int u0p1 = ut * 32;
    const int k0p1 = ks * 512;
    // P2 role: u-tile 32, k quarter 256
    const int ut2  = bid >> 2;
    const int ks2  = bid & 3;
    const int u0p2 = ut2 * 32;
    const int k0p2 = ks2 * 256;

    // preload U slices (resident all 512 steps)
    for (int i = tid; i < 512 * 8; i += 512) {
        int kk = i >> 3, uu4 = (i & 7) * 4;
        *(float4*)&Ug[kk * 32 + uu4] =
            *(const float4*)&U[(size_t)(k0p1 + kk) * NG_ + g * UN_ + u0p1 + uu4];
    }
    for (int i = tid; i < 256 * 8; i += 512) {
        int kk = i >> 3, uu4 = (i & 7) * 4;
        *(float4*)&Uh2[kk * 32 + uu4] =
            *(const float4*)&U[(size_t)(k0p2 + kk) * NG_ + 2 * UN_ + u0p2 + uu4];
    }
    __syncthreads();

    const int uq  = tid & 7;          // 4 u's at uq*4
    const int bq  = (tid >> 3) & 7;   // 4 b's at bq*4 (2 f32x2 pairs)
    const int kx  = tid >> 6;         // 8-way in-block k split
    const int r64 = tid & 63;

    unsigned long long epoch = 0;

    for (int t = 0; t < T_; t++) {
        // ================= P1: z,r partials =================
        ull acc2[2][4];
#pragma unroll
        for (int p = 0; p < 2; p++)
#pragma unroll
            for (int j = 0; j < 4; j++) acc2[p][j] = 0ULL;

        for (int kc = 0; kc < 4; kc++) {
            const int kbase = k0p1 + kc * 128;
            __syncthreads();
            for (int i = tid; i < 1024; i += 512) {
                int b = i & 31, k4 = i >> 5;
                float4 hv = __ldcg((const float4*)&g_h[b * UN_ + kbase + k4 * 4]);
                hsT[(k4 * 4 + 0) * 32 + b] = hv.x;
                hsT[(k4 * 4 + 1) * 32 + b] = hv.y;
                hsT[(k4 * 4 + 2) * 32 + b] = hv.z;
                hsT[(k4 * 4 + 3) * 32 + b] = hv.w;
            }
            __syncthreads();
#pragma unroll 4
            for (int kk = kx; kk < 128; kk += 8) {
                float uv[4];
                *(float4*)uv = *(float4*)&Ug[(kc * 128 + kk) * 32 + uq * 4];
                ulonglong2 hp = *(ulonglong2*)&hsT[kk * 32 + bq * 4];
#pragma unroll
                for (int j = 0; j < 4; j++) {
                    ull dj; DUP2(dj, __float_as_uint(uv[j]));
                    FMA2(acc2[0][j], hp.x, dj);
                    FMA2(acc2[1][j], hp.y, dj);
                }
            }
        }
        __syncthreads();
        if (kx > 0) {
            ull* d = redu + (size_t)(kx - 1) * 8 * 64;
#pragma unroll
            for (int q = 0; q < 8; q++) d[q * 64 + r64] = acc2[q >> 2][q & 3];
        }
        __syncthreads();
        if (kx == 0) {
#pragma unroll
            for (int s = 0; s < 7; s++)
#pragma unroll
                for (int q = 0; q < 8; q++)
                    ADD2(acc2[q >> 2][q & 3], redu[(s * 8 + q) * 64 + r64]);
#pragma unroll
            for (int i = 0; i < 4; i++) {
                int p = i >> 1, hh = i & 1;
                F2U a0, a1, a2, a3;
                a0.u = acc2[p][0]; a1.u = acc2[p][1]; a2.u = acc2[p][2]; a3.u = acc2[p][3];
                float4 v = {a0.f[hh], a1.f[hh], a2.f[hh], a3.f[hh]};
                __stcg((float4*)&g_p1[((g * 2 + ks) * B_ + bq * 4 + i) * UN_ + u0p1 + uq * 4], v);
            }
        }
        __syncthreads();
        if (tid == 0) {
            __threadfence();
            unsigned long long old = atomicAdd(&g_c1[g * 32 + ut], 1ULL);
            sflag = (int)(old & 1ULL);
        }
        __syncthreads();
        if (sflag) {
            __threadfence();
            for (int i = tid; i < 1024; i += 512) {
                int b = i >> 5, u = u0p1 + (i & 31);
                float s = __ldcg(&g_p1[((g * 2 + 0) * B_ + b) * UN_ + u]) +
                          __ldcg(&g_p1[((g * 2 + 1) * B_ + b) * UN_ + u]);
                int col = g * UN_ + u;
                s += __ldcg(&g_xp[((size_t)b * T_ + t) * NG_ + col]) + g_bsum[col];
                float sig = 1.f / (1.f + __expf(-s));
                if (g == 0) __stcg(&g_z[b * UN_ + u], sig);
                else        __stcg(&g_rh[b * UN_ + u], sig * __ldcg(&g_h[b * UN_ + u]));
            }
        }
        epoch++; gridbar(epoch * NBLK);

        // ================= P2: hcand partials =================
        ull a2v[2][4];
#pragma unroll
        for (int p = 0; p < 2; p++)
#pragma unroll
            for (int j = 0; j < 4; j++) a2v[p][j] = 0ULL;

        for (int kc = 0; kc < 2; kc++) {
            const int kbase = k0p2 + kc * 128;
            __syncthreads();
            for (int i = tid; i < 1024; i += 512) {
                int b = i & 31, k4 = i >> 5;
                float4 hv = __ldcg((const float4*)&g_rh[b * UN_ + kbase + k4 * 4]);
                hsT[(k4 * 4 + 0) * 32 + b] = hv.x;
                hsT[(k4 * 4 + 1) * 32 + b] = hv.y;
                hsT[(k4 * 4 + 2) * 32 + b] = hv.z;
                hsT[(k4 * 4 + 3) * 32 + b] = hv.w;
            }
            __syncthreads();
#pragma unroll 4
            for (int kk = kx; kk < 128; kk += 8) {
                float uv[4];
                *(float4*)uv = *(float4*)&Uh2[(kc * 128 + kk) * 32 + uq * 4];
                ulonglong2 hp = *(ulonglong2*)&hsT[kk * 32 + bq * 4];
#pragma unroll
                for (int j = 0; j < 4; j++) {
                    ull dj; DUP2(dj, __float_as_uint(uv[j]));
                    FMA2(a2v[0][j], hp.x, dj);
                    FMA2(a2v[1][j], hp.y, dj);
                }
            }
        }
        __syncthreads();
        if (kx > 0) {
            ull* d = redu + (size_t)(kx - 1) * 8 * 64;
#pragma unroll
            for (int q = 0; q < 8; q++) d[q * 64 + r64] = a2v[q >> 2][q & 3];
        }
        __syncthreads();
        if (kx == 0) {
#pragma unroll
            for (int s = 0; s < 7; s++)
#pragma unroll
                for (int q = 0; q < 8; q++)
                    ADD2(a2v[q >> 2][q & 3], redu[(s * 8 + q) * 64 + r64]);
#pragma unroll
            for (int i = 0; i < 4; i++) {
                int p = i >> 1, hh = i & 1;
                F2U a0, a1, a2, a3;
                a0.u = a2v[p][0]; a1.u = a2v[p][1]; a2.u = a2v[p][2]; a3.u = a2v[p][3];
                float4 v = {a0.f[hh], a1.f[hh], a2.f[hh], a3.f[hh]};
                __stcg((float4*)&g_p2[(ks2 * B_ + bq * 4 + i) * UN_ + u0p2 + uq * 4], v);
            }
        }
        __syncthreads();
        if (tid == 0) {
            __threadfence();
            unsigned long long old = atomicAdd(&g_c2[ut2], 1ULL);
            sflag = ((old & 3ULL) == 3ULL) ? 1 : 0;
        }
        __syncthreads();
        if (sflag) {
            __threadfence();
            for (int i = tid; i < 1024; i += 512) {
                int b = i >> 5, u = u0p2 + (i & 31);
                float s = __ldcg(&g_p2[(0 * B_ + b) * UN_ + u]) +
                          __ldcg(&g_p2[(1 * B_ + b) * UN_ + u]) +
                          __ldcg(&g_p2[(2 * B_ + b) * UN_ + u]) +
                          __ldcg(&g_p2[(3 * B_ + b) * UN_ + u]);
                int col = 2 * UN_ + u;
                s += __ldcg(&g_xp[((size_t)b * T_ + t) * NG_ + col]) + g_bsum[col];
                float hc = tanhf(s);
                float z  = __ldcg(&g_z[b * UN_ + u]);
                float ho = __ldcg(&g_h[b * UN_ + u]);
                float hn = z * ho + (1.f - z) * hc;
                __stcg(&g_h[b * UN_ + u], hn);
                out[((size_t)b * T_ + t) * UN_ + u] = hn;
            }
        }
        epoch++; gridbar(epoch * NBLK);
    }

    // final hidden state hT
    for (int i = bid * 512 + tid; i < B_ * UN_; i += NBLK * 512)
        out[(size_t)B_ * T_ * UN_ + i] = __ldcg(&g_h[i]);
}

// ---------------- launcher ----------------
extern "C" void kernel_launch(void* const* d_in, const int* in_sizes, int n_in,
                              void* d_out, int out_size) {
    const float* x  = (const float*)d_in[0];
    const float* W  = (const float*)d_in[1];
    const float* U  = (const float*)d_in[2];
    const float* b  = (const float*)d_in[3];
    const float* h0 = (const float*)d_in[4];
    float* out = (float*)d_out;

    static bool attr_done = false;
    if (!attr_done) {
        cudaFuncSetAttribute(k_gru, cudaFuncAttributeMaxDynamicSharedMemorySize,
                             SM_FLOATS * sizeof(float));
        attr_done = true;
    }

    k_bsum<<<NG_ / 256, 256>>>(b);
    k_init<<<NBLK, 256>>>(h0);
    {
        dim3 grid(NG_ / 128, M_ / 128);
        k_gemm<<<grid, 256>>>(x, W);
    }
    k_gru<<<NBLK, 512, SM_FLOATS * sizeof(float)>>>(U, out);
}